// round 1
// baseline (speedup 1.0000x reference)
#include <cuda_runtime.h>

#define BB 8
#define TT 2048
#define CC 1024
#define HH 64

// scratch for projected q, k, v (allocation-free rule -> device globals)
__device__ float g_q[BB*TT*HH];
__device__ float g_k[BB*TT*HH];
__device__ float g_v[BB*TT*HH];

// ---------------------------------------------------------------------------
// Projection: q/k/v = x @ Wq/Wk/Wv, fused (x read once).
// Block: 256 threads = 16x16, each thread computes 4x4 per output matrix.
// M tile = 64 rows, N = 64 (full H), K chunked by 32 through smem.
// ---------------------------------------------------------------------------
__global__ __launch_bounds__(256, 1) void proj_kernel(
    const float* __restrict__ x, const float* __restrict__ Wq,
    const float* __restrict__ Wk, const float* __restrict__ Wv)
{
    __shared__ float xs[64][33];       // +1 pad
    __shared__ float wq_s[32][64];
    __shared__ float wk_s[32][64];
    __shared__ float wv_s[32][64];

    const int tid = threadIdx.x;
    const int ty = tid >> 4, tx = tid & 15;
    const size_t row0 = (size_t)blockIdx.x * 64;

    float aq[4][4] = {}, ak[4][4] = {}, av[4][4] = {};

    for (int k0 = 0; k0 < CC; k0 += 32) {
        __syncthreads();
        #pragma unroll
        for (int i = 0; i < 8; i++) {
            int idx = tid + i*256;
            int r = idx >> 5, c = idx & 31;
            xs[r][c] = x[(row0 + r)*CC + (k0 + c)];
        }
        #pragma unroll
        for (int i = 0; i < 8; i++) {
            int idx = tid + i*256;
            int r = idx >> 6, c = idx & 63;
            wq_s[r][c] = Wq[(size_t)(k0 + r)*HH + c];
            wk_s[r][c] = Wk[(size_t)(k0 + r)*HH + c];
            wv_s[r][c] = Wv[(size_t)(k0 + r)*HH + c];
        }
        __syncthreads();
        #pragma unroll
        for (int kk = 0; kk < 32; kk++) {
            float a[4];
            #pragma unroll
            for (int i = 0; i < 4; i++) a[i] = xs[ty*4+i][kk];
            float4 bq = *(const float4*)&wq_s[kk][tx*4];
            float4 bk = *(const float4*)&wk_s[kk][tx*4];
            float4 bv = *(const float4*)&wv_s[kk][tx*4];
            #pragma unroll
            for (int i = 0; i < 4; i++) {
                aq[i][0] += a[i]*bq.x; aq[i][1] += a[i]*bq.y;
                aq[i][2] += a[i]*bq.z; aq[i][3] += a[i]*bq.w;
                ak[i][0] += a[i]*bk.x; ak[i][1] += a[i]*bk.y;
                ak[i][2] += a[i]*bk.z; ak[i][3] += a[i]*bk.w;
                av[i][0] += a[i]*bv.x; av[i][1] += a[i]*bv.y;
                av[i][2] += a[i]*bv.z; av[i][3] += a[i]*bv.w;
            }
        }
    }
    #pragma unroll
    for (int i = 0; i < 4; i++) {
        size_t off = (row0 + ty*4 + i)*HH + tx*4;
        *(float4*)&g_q[off] = make_float4(aq[i][0],aq[i][1],aq[i][2],aq[i][3]);
        *(float4*)&g_k[off] = make_float4(ak[i][0],ak[i][1],ak[i][2],ak[i][3]);
        *(float4*)&g_v[off] = make_float4(av[i][0],av[i][1],av[i][2],av[i][3]);
    }
}

// ---------------------------------------------------------------------------
// Flash attention (causal), Br = Bc = 64, fp32.
// Grid: (T/64, B). Block: 256 threads = 16x16; each thread owns 4 rows x 4 cols
// of both S (64x64) and O (64x64). Row reductions via shfl within the 16-lane
// thread-row (stays inside a half-warp). Only kt <= qt tiles are visited.
// ---------------------------------------------------------------------------
__global__ __launch_bounds__(256, 1) void attn_kernel(float* __restrict__ out)
{
    extern __shared__ float sm[];
    float* Qs = sm;                  // 64 x 65
    float* Ks = Qs + 64*65;          // 64 x 65
    float* Ss = Ks + 64*65;          // 64 x 65 (P tile)
    float* Vs = Ss + 64*65;          // 64 x 64 (stride 64 for aligned float4)

    const int tid = threadIdx.x;
    const int ty = tid >> 4, tx = tid & 15;
    const int b  = blockIdx.y;
    const int qt = blockIdx.x;
    const int r0 = qt*64;
    const float* qg = g_q + (size_t)b*TT*HH;
    const float* kg = g_k + (size_t)b*TT*HH;
    const float* vg = g_v + (size_t)b*TT*HH;

    #pragma unroll
    for (int i = 0; i < 16; i++) {
        int idx = tid + i*256;
        int r = idx >> 6, c = idx & 63;
        Qs[r*65+c] = qg[(size_t)(r0 + r)*HH + c];
    }

    float o[4][4] = {};
    float m_i[4] = {-1e30f, -1e30f, -1e30f, -1e30f};
    float l_i[4] = {};

    for (int kt = 0; kt <= qt; kt++) {
        const int c0 = kt*64;
        __syncthreads();   // protect Ks/Vs/Ss from previous iteration's readers
        #pragma unroll
        for (int i = 0; i < 16; i++) {
            int idx = tid + i*256;
            int r = idx >> 6, c = idx & 63;
            Ks[r*65+c] = kg[(size_t)(c0 + r)*HH + c];
            Vs[r*64+c] = vg[(size_t)(c0 + r)*HH + c];
        }
        __syncthreads();

        // S = Q K^T  (4x4 per thread)
        float s[4][4] = {};
        #pragma unroll
        for (int h = 0; h < HH; h++) {
            float a[4], bk[4];
            #pragma unroll
            for (int i = 0; i < 4; i++) a[i]  = Qs[(ty*4+i)*65 + h];
            #pragma unroll
            for (int j = 0; j < 4; j++) bk[j] = Ks[(tx*4+j)*65 + h];
            #pragma unroll
            for (int i = 0; i < 4; i++)
                #pragma unroll
                for (int j = 0; j < 4; j++)
                    s[i][j] += a[i]*bk[j];
        }

        const float scale = 0.125f;  // 1/sqrt(64)
        if (kt == qt) {
            #pragma unroll
            for (int i = 0; i < 4; i++)
                #pragma unroll
                for (int j = 0; j < 4; j++)
                    s[i][j] = (c0 + tx*4 + j > r0 + ty*4 + i) ? -1e30f
                                                              : s[i][j]*scale;
        } else {
            #pragma unroll
            for (int i = 0; i < 4; i++)
                #pragma unroll
                for (int j = 0; j < 4; j++)
                    s[i][j] *= scale;
        }

        // online softmax update per owned row
        #pragma unroll
        for (int i = 0; i < 4; i++) {
            float mt = fmaxf(fmaxf(s[i][0], s[i][1]), fmaxf(s[i][2], s[i][3]));
            mt = fmaxf(mt, __shfl_xor_sync(0xffffffffu, mt, 8));
            mt = fmaxf(mt, __shfl_xor_sync(0xffffffffu, mt, 4));
            mt = fmaxf(mt, __shfl_xor_sync(0xffffffffu, mt, 2));
            mt = fmaxf(mt, __shfl_xor_sync(0xffffffffu, mt, 1));
            float mnew = fmaxf(m_i[i], mt);
            float corr = __expf(m_i[i] - mnew);
            m_i[i] = mnew;
            float rs = 0.f;
            #pragma unroll
            for (int j = 0; j < 4; j++) {
                s[i][j] = __expf(s[i][j] - mnew);
                rs += s[i][j];
            }
            rs += __shfl_xor_sync(0xffffffffu, rs, 8);
            rs += __shfl_xor_sync(0xffffffffu, rs, 4);
            rs += __shfl_xor_sync(0xffffffffu, rs, 2);
            rs += __shfl_xor_sync(0xffffffffu, rs, 1);
            l_i[i] = l_i[i]*corr + rs;
            #pragma unroll
            for (int j = 0; j < 4; j++) {
                o[i][j] *= corr;
                Ss[(ty*4+i)*65 + tx*4 + j] = s[i][j];
            }
        }
        __syncthreads();

        // O += P V  (P broadcast across thread-row; V float4, conflict-free)
        #pragma unroll
        for (int kk = 0; kk < 64; kk++) {
            float p[4];
            #pragma unroll
            for (int i = 0; i < 4; i++) p[i] = Ss[(ty*4+i)*65 + kk];
            float4 vv = *(const float4*)&Vs[kk*64 + tx*4];
            #pragma unroll
            for (int i = 0; i < 4; i++) {
                o[i][0] += p[i]*vv.x;
                o[i][1] += p[i]*vv.y;
                o[i][2] += p[i]*vv.z;
                o[i][3] += p[i]*vv.w;
            }
        }
    }

    #pragma unroll
    for (int i = 0; i < 4; i++) {
        float inv = 1.0f / l_i[i];
        size_t off = ((size_t)b*TT + r0 + ty*4 + i)*HH + tx*4;
        *(float4*)&out[off] = make_float4(o[i][0]*inv, o[i][1]*inv,
                                          o[i][2]*inv, o[i][3]*inv);
    }
}

extern "C" void kernel_launch(void* const* d_in, const int* in_sizes, int n_in,
                              void* d_out, int out_size) {
    const float* x  = (const float*)d_in[0];
    const float* Wk = (const float*)d_in[1];
    const float* Wq = (const float*)d_in[2];
    const float* Wv = (const float*)d_in[3];
    float* out = (float*)d_out;

    proj_kernel<<<(BB*TT)/64, 256>>>(x, Wq, Wk, Wv);

    const int smem = (3*64*65 + 64*64) * (int)sizeof(float);  // 65792 B
    cudaFuncSetAttribute(attn_kernel,
                         cudaFuncAttributeMaxDynamicSharedMemorySize, smem);
    dim3 grid(TT/64, BB);
    attn_kernel<<<grid, 256, smem>>>(out);
}